// round 5
// baseline (speedup 1.0000x reference)
#include <cuda_runtime.h>
#include <cuda_bf16.h>

// ---------------------------------------------------------------------------
// BiRNN: RNN1 (bidirectional, H=9, D=5, T=2048) -> RNN2 (H=32, 25 steps) -> out
// Strategy: one thread per (batch, direction) chain for RNN1, all weights in
// registers, f32x2 packed FMAs (i-dimension paired), tanh via EX2+RCP with
// weights pre-scaled by 2*log2(e). RNN2: one warp per batch, shfl-broadcast.
// ---------------------------------------------------------------------------

typedef unsigned long long u64t;

__device__ float g_y[4096 * 18];  // concat(h_fwd, h_bwd) staging

static constexpr float SC = 2.8853900817779268f;  // 2 * log2(e)

__device__ __forceinline__ u64t pk2(float lo, float hi) {
    u64t r;
    asm("mov.b64 %0, {%1, %2};" : "=l"(r) : "f"(lo), "f"(hi));
    return r;
}
__device__ __forceinline__ void upk2(u64t v, float& lo, float& hi) {
    asm("mov.b64 {%0, %1}, %2;" : "=f"(lo), "=f"(hi) : "l"(v));
}
__device__ __forceinline__ u64t f2fma(u64t a, u64t b, u64t c) {
    u64t r;
    asm("fma.rn.f32x2 %0, %1, %2, %3;" : "=l"(r) : "l"(a), "l"(b), "l"(c));
    return r;
}
__device__ __forceinline__ float ex2f_(float x) {
    float r; asm("ex2.approx.f32 %0, %1;" : "=f"(r) : "f"(x)); return r;
}
__device__ __forceinline__ float rcpf_(float x) {
    float r; asm("rcp.approx.f32 %0, %1;" : "=f"(r) : "f"(x)); return r;
}
// s = 2*log2(e)*a ; returns tanh(a) = 1 - 2/(exp(2a)+1)
__device__ __forceinline__ float tanh_sc(float s) {
    float e = ex2f_(s);
    return fmaf(-2.0f, rcpf_(e + 1.0f), 1.0f);
}

// ---------------------------------------------------------------------------
// RNN1 body: one thread = one chain. BACK selects time direction.
// ---------------------------------------------------------------------------
template <bool BACK>
__device__ __forceinline__ void rnn1_body(
    int b, const float* __restrict__ x,
    const float* __restrict__ wih, const float* __restrict__ whh,
    const float* __restrict__ bih, const float* __restrict__ bhh, int T)
{
    // ---- load & pack weights (pre-scaled by SC), i-dim paired (0,1)(2,3)(4,5)(6,7) + scalar row 8
    u64t WH[4][9]; float WH8[9];
    u64t WI[4][5]; float WI8[5];
    u64t BP[4];    float B8;
#pragma unroll
    for (int j = 0; j < 9; j++) {
#pragma unroll
        for (int p = 0; p < 4; p++)
            WH[p][j] = pk2(SC * __ldg(whh + (2 * p) * 9 + j),
                           SC * __ldg(whh + (2 * p + 1) * 9 + j));
        WH8[j] = SC * __ldg(whh + 72 + j);
    }
#pragma unroll
    for (int d = 0; d < 5; d++) {
#pragma unroll
        for (int p = 0; p < 4; p++)
            WI[p][d] = pk2(SC * __ldg(wih + (2 * p) * 5 + d),
                           SC * __ldg(wih + (2 * p + 1) * 5 + d));
        WI8[d] = SC * __ldg(wih + 40 + d);
    }
#pragma unroll
    for (int p = 0; p < 4; p++)
        BP[p] = pk2(SC * (__ldg(bih + 2 * p) + __ldg(bhh + 2 * p)),
                    SC * (__ldg(bih + 2 * p + 1) + __ldg(bhh + 2 * p + 1)));
    B8 = SC * (__ldg(bih + 8) + __ldg(bhh + 8));

    // ---- state
    float hs[9];
    u64t  hb[9];
#pragma unroll
    for (int i = 0; i < 9; i++) { hs[i] = 0.0f; hb[i] = 0ULL; }

    const int G = T >> 2;  // 4 timesteps per group = 20 floats = 5 float4
    const float4* xp = reinterpret_cast<const float4*>(x) + (size_t)b * ((size_t)T * 5 / 4);

    float bufA[20], bufB[20];

    auto LOAD = [&](float* buf, int g) {
        int base = BACK ? 5 * (G - 1 - g) : 5 * g;
#pragma unroll
        for (int k = 0; k < 5; k++) {
            float4 v = __ldg(xp + base + k);
            buf[4 * k + 0] = v.x; buf[4 * k + 1] = v.y;
            buf[4 * k + 2] = v.z; buf[4 * k + 3] = v.w;
        }
    };

    auto STEP = [&](const float* buf, int off) {
        u64t a0 = BP[0], a1 = BP[1], a2 = BP[2], a3 = BP[3];
        float a8 = B8;
#pragma unroll
        for (int j = 0; j < 9; j++) {
            a0 = f2fma(WH[0][j], hb[j], a0);
            a1 = f2fma(WH[1][j], hb[j], a1);
            a2 = f2fma(WH[2][j], hb[j], a2);
            a3 = f2fma(WH[3][j], hb[j], a3);
            a8 = fmaf(WH8[j], hs[j], a8);
        }
#pragma unroll
        for (int d = 0; d < 5; d++) {
            float xv = buf[off + d];
            u64t xb = pk2(xv, xv);
            a0 = f2fma(WI[0][d], xb, a0);
            a1 = f2fma(WI[1][d], xb, a1);
            a2 = f2fma(WI[2][d], xb, a2);
            a3 = f2fma(WI[3][d], xb, a3);
            a8 = fmaf(WI8[d], xv, a8);
        }
        float s0, s1;
        upk2(a0, s0, s1); hs[0] = tanh_sc(s0); hs[1] = tanh_sc(s1);
        upk2(a1, s0, s1); hs[2] = tanh_sc(s0); hs[3] = tanh_sc(s1);
        upk2(a2, s0, s1); hs[4] = tanh_sc(s0); hs[5] = tanh_sc(s1);
        upk2(a3, s0, s1); hs[6] = tanh_sc(s0); hs[7] = tanh_sc(s1);
        hs[8] = tanh_sc(a8);
#pragma unroll
        for (int i = 0; i < 9; i++) hb[i] = pk2(hs[i], hs[i]);
    };

    LOAD(bufA, 0);
    for (int g = 0; g < G; g += 2) {
        if (g + 1 < G) LOAD(bufB, g + 1);
#pragma unroll
        for (int s = 0; s < 4; s++) STEP(bufA, (BACK ? (3 - s) : s) * 5);
        if (g + 2 < G) LOAD(bufA, g + 2);
#pragma unroll
        for (int s = 0; s < 4; s++) STEP(bufB, (BACK ? (3 - s) : s) * 5);
    }

    float* dst = g_y + (size_t)b * 18 + (BACK ? 9 : 0);
#pragma unroll
    for (int i = 0; i < 9; i++) dst[i] = hs[i];
}

__global__ void __launch_bounds__(128, 1) rnn1_kernel(
    const float* __restrict__ x,
    const float* __restrict__ wih_f, const float* __restrict__ whh_f,
    const float* __restrict__ bih_f, const float* __restrict__ bhh_f,
    const float* __restrict__ wih_b, const float* __restrict__ whh_b,
    const float* __restrict__ bih_b, const float* __restrict__ bhh_b,
    int T)
{
    int half = gridDim.x >> 1;
    if (blockIdx.x >= half) {
        int b = (blockIdx.x - half) * blockDim.x + threadIdx.x;
        rnn1_body<true>(b, x, wih_b, whh_b, bih_b, bhh_b, T);
    } else {
        int b = blockIdx.x * blockDim.x + threadIdx.x;
        rnn1_body<false>(b, x, wih_f, whh_f, bih_f, bhh_f, T);
    }
}

// ---------------------------------------------------------------------------
// RNN2 + output projection: one warp per batch, lane i owns hidden unit i.
// ---------------------------------------------------------------------------
__global__ void __launch_bounds__(128) rnn2_kernel(
    const float* __restrict__ wih2, const float* __restrict__ whh2,
    const float* __restrict__ bih2, const float* __restrict__ bhh2,
    const float* __restrict__ wout, const float* __restrict__ bout,
    float* __restrict__ out, int B)
{
    int gw = (blockIdx.x * blockDim.x + threadIdx.x) >> 5;
    int lane = threadIdx.x & 31;
    if (gw >= B) return;

    float WHR[32], WIR[18];
#pragma unroll
    for (int j = 0; j < 32; j++) WHR[j] = SC * __ldg(whh2 + lane * 32 + j);
#pragma unroll
    for (int j = 0; j < 18; j++) WIR[j] = SC * __ldg(wih2 + lane * 18 + j);
    float bi = SC * (__ldg(bih2 + lane) + __ldg(bhh2 + lane));
    float wo0 = __ldg(wout + lane);
    float wo1 = __ldg(wout + 32 + lane);
    float wo2 = __ldg(wout + 64 + lane);
    float bo0 = __ldg(bout + 0), bo1 = __ldg(bout + 1), bo2 = __ldg(bout + 2);

    const float* yb = g_y + (size_t)gw * 18;
    float acc = bi;
#pragma unroll
    for (int j = 0; j < 18; j++) acc = fmaf(WIR[j], __ldg(yb + j), acc);
    float h = tanh_sc(acc);

    float* ob = out + (size_t)gw * 75;
#pragma unroll 1
    for (int t = 0; t < 25; t++) {
        float p0 = wo0 * h, p1 = wo1 * h, p2 = wo2 * h;
#pragma unroll
        for (int off = 16; off; off >>= 1) {
            p0 += __shfl_xor_sync(0xffffffffu, p0, off);
            p1 += __shfl_xor_sync(0xffffffffu, p1, off);
            p2 += __shfl_xor_sync(0xffffffffu, p2, off);
        }
        if (lane == 0) {
            ob[t * 3 + 0] = p0 + bo0;
            ob[t * 3 + 1] = p1 + bo1;
            ob[t * 3 + 2] = p2 + bo2;
        }
        if (t < 24) {
            float a = bi;
#pragma unroll
            for (int j = 0; j < 32; j++)
                a = fmaf(WHR[j], __shfl_sync(0xffffffffu, h, j), a);
            h = tanh_sc(a);
        }
    }
}

// ---------------------------------------------------------------------------
extern "C" void kernel_launch(void* const* d_in, const int* in_sizes, int n_in,
                              void* d_out, int out_size)
{
    const float* x      = (const float*)d_in[0];
    const float* wih_f  = (const float*)d_in[1];
    const float* whh_f  = (const float*)d_in[2];
    const float* bih_f  = (const float*)d_in[3];
    const float* bhh_f  = (const float*)d_in[4];
    const float* wih_b  = (const float*)d_in[5];
    const float* whh_b  = (const float*)d_in[6];
    const float* bih_b  = (const float*)d_in[7];
    const float* bhh_b  = (const float*)d_in[8];
    const float* wih2   = (const float*)d_in[9];
    const float* whh2   = (const float*)d_in[10];
    const float* bih2   = (const float*)d_in[11];
    const float* bhh2   = (const float*)d_in[12];
    const float* wout   = (const float*)d_in[13];
    const float* bout   = (const float*)d_in[14];
    float* out = (float*)d_out;

    int B = out_size / 75;                 // 4096
    int T = in_sizes[0] / (B * 5);         // 2048

    int half = B / 128;                    // 32 blocks per direction
    rnn1_kernel<<<2 * half, 128>>>(x, wih_f, whh_f, bih_f, bhh_f,
                                   wih_b, whh_b, bih_b, bhh_b, T);

    int blocks2 = (B * 32) / 128;          // one warp per batch
    rnn2_kernel<<<blocks2, 128>>>(wih2, whh2, bih2, bhh2, wout, bout, out, B);
}

// round 6
// speedup vs baseline: 1.3331x; 1.3331x over previous
#include <cuda_runtime.h>
#include <cuda_bf16.h>

// ---------------------------------------------------------------------------
// BiRNN R6: RNN1 split 2 lanes/chain (uniform code via per-lane permuted
// weights, f32x2 pairs, redundant h8), RNN2 via smem broadcast (no shuffles).
// ---------------------------------------------------------------------------

typedef unsigned long long u64t;

__device__ float g_y[4096 * 18];  // concat(h_fwd, h_bwd) staging

static constexpr float SC = 2.8853900817779268f;  // 2 * log2(e)

__device__ __forceinline__ u64t pk2(float lo, float hi) {
    u64t r;
    asm("mov.b64 %0, {%1, %2};" : "=l"(r) : "f"(lo), "f"(hi));
    return r;
}
__device__ __forceinline__ void upk2(u64t v, float& lo, float& hi) {
    asm("mov.b64 {%0, %1}, %2;" : "=f"(lo), "=f"(hi) : "l"(v));
}
__device__ __forceinline__ u64t f2fma(u64t a, u64t b, u64t c) {
    u64t r;
    asm("fma.rn.f32x2 %0, %1, %2, %3;" : "=l"(r) : "l"(a), "l"(b), "l"(c));
    return r;
}
__device__ __forceinline__ float ex2f_(float x) {
    float r; asm("ex2.approx.f32 %0, %1;" : "=f"(r) : "f"(x)); return r;
}
__device__ __forceinline__ float rcpf_(float x) {
    float r; asm("rcp.approx.f32 %0, %1;" : "=f"(r) : "f"(x)); return r;
}
// s = 2*log2(e)*a ; tanh(a) = 1 - 2/(exp(2a)+1), exact identity, approx units
__device__ __forceinline__ float tanh_sc(float s) {
    float e = ex2f_(s);
    return fmaf(-2.0f, rcpf_(e + 1.0f), 1.0f);
}

// ---------------------------------------------------------------------------
// RNN1: two lanes per chain. Lane r owns outputs {4r..4r+3} as 2 f32x2 pairs;
// both lanes compute output 8 redundantly (identical -> no exchange needed).
// Weight columns permuted per-lane: local h slot k -> global column colmap[k]:
//   k<4 : 4r+k (own), 4<=k<8 : 4(1-r)+(k-4) (remote), k=8 : 8.
// ---------------------------------------------------------------------------
template <bool BACK>
__device__ __forceinline__ void rnn1_body(
    int b, int r, const float* __restrict__ x,
    const float* __restrict__ wih, const float* __restrict__ whh,
    const float* __restrict__ bih, const float* __restrict__ bhh, int T)
{
    const int own = 4 * r;        // first own row
    const int rem = 4 * (1 - r);  // partner's first row

    // ---- weights (pre-scaled by SC), per-lane permuted columns
    u64t  WH0[9], WH1[9];  float WH8[9];
    u64t  WI0[5], WI1[5];  float WI8[5];
#pragma unroll
    for (int k = 0; k < 9; k++) {
        int c = (k < 4) ? (own + k) : ((k < 8) ? (rem + (k - 4)) : 8);
        WH0[k] = pk2(SC * __ldg(whh + (own + 0) * 9 + c),
                     SC * __ldg(whh + (own + 1) * 9 + c));
        WH1[k] = pk2(SC * __ldg(whh + (own + 2) * 9 + c),
                     SC * __ldg(whh + (own + 3) * 9 + c));
        WH8[k] = SC * __ldg(whh + 72 + c);
    }
#pragma unroll
    for (int d = 0; d < 5; d++) {
        WI0[d] = pk2(SC * __ldg(wih + (own + 0) * 5 + d),
                     SC * __ldg(wih + (own + 1) * 5 + d));
        WI1[d] = pk2(SC * __ldg(wih + (own + 2) * 5 + d),
                     SC * __ldg(wih + (own + 3) * 5 + d));
        WI8[d] = SC * __ldg(wih + 40 + d);
    }
    u64t BI0 = pk2(SC * (__ldg(bih + own + 0) + __ldg(bhh + own + 0)),
                   SC * (__ldg(bih + own + 1) + __ldg(bhh + own + 1)));
    u64t BI1 = pk2(SC * (__ldg(bih + own + 2) + __ldg(bhh + own + 2)),
                   SC * (__ldg(bih + own + 3) + __ldg(bhh + own + 3)));
    float B8 = SC * (__ldg(bih + 8) + __ldg(bhh + 8));

    // ---- state (local-permuted h view)
    float vs[9];
    u64t  vb[9];
#pragma unroll
    for (int i = 0; i < 9; i++) { vs[i] = 0.0f; vb[i] = 0ULL; }

    const int G = T >> 2;  // 4 timesteps per group = 20 floats = 5 float4
    const float4* xp = reinterpret_cast<const float4*>(x) + (size_t)b * ((size_t)T * 5 / 4);

    float bufA[20], bufB[20];

    auto LOAD = [&](float* buf, int g) {
        int base = BACK ? 5 * (G - 1 - g) : 5 * g;
#pragma unroll
        for (int k = 0; k < 5; k++) {
            float4 v = __ldg(xp + base + k);
            buf[4 * k + 0] = v.x; buf[4 * k + 1] = v.y;
            buf[4 * k + 2] = v.z; buf[4 * k + 3] = v.w;
        }
    };

    auto STEP = [&](const float* buf, int off) {
        u64t a0 = BI0, a1 = BI1;
        float a8 = B8;
        // x-contribution first: independent of h -> off the critical path
#pragma unroll
        for (int d = 0; d < 5; d++) {
            float xv = buf[off + d];
            u64t xb = pk2(xv, xv);
            a0 = f2fma(WI0[d], xb, a0);
            a1 = f2fma(WI1[d], xb, a1);
            a8 = fmaf(WI8[d], xv, a8);
        }
        // h-contribution: own slots (ready first) then remote (arrive via shfl)
#pragma unroll
        for (int k = 0; k < 9; k++) {
            a0 = f2fma(WH0[k], vb[k], a0);
            a1 = f2fma(WH1[k], vb[k], a1);
            a8 = fmaf(WH8[k], vs[k], a8);
        }
        float s0, s1, o0, o1, o2, o3;
        upk2(a0, s0, s1); o0 = tanh_sc(s0); o1 = tanh_sc(s1);
        upk2(a1, s0, s1); o2 = tanh_sc(s0); o3 = tanh_sc(s1);
        float o8 = tanh_sc(a8);
        // exchange the 4 own outputs with the partner lane
        float r0 = __shfl_xor_sync(0xffffffffu, o0, 1);
        float r1 = __shfl_xor_sync(0xffffffffu, o1, 1);
        float r2 = __shfl_xor_sync(0xffffffffu, o2, 1);
        float r3 = __shfl_xor_sync(0xffffffffu, o3, 1);
        vs[0] = o0; vs[1] = o1; vs[2] = o2; vs[3] = o3;
        vs[4] = r0; vs[5] = r1; vs[6] = r2; vs[7] = r3;
        vs[8] = o8;
#pragma unroll
        for (int i = 0; i < 9; i++) vb[i] = pk2(vs[i], vs[i]);
    };

    LOAD(bufA, 0);
    for (int g = 0; g < G; g += 2) {
        if (g + 1 < G) LOAD(bufB, g + 1);
#pragma unroll
        for (int s = 0; s < 4; s++) STEP(bufA, (BACK ? (3 - s) : s) * 5);
        if (g + 2 < G) LOAD(bufA, g + 2);
#pragma unroll
        for (int s = 0; s < 4; s++) STEP(bufB, (BACK ? (3 - s) : s) * 5);
    }

    // writeback: own 4 values at global rows own..own+3; h8 written by both
    // lanes (bitwise-identical computation -> benign duplicate store)
    float* dst = g_y + (size_t)b * 18 + (BACK ? 9 : 0);
#pragma unroll
    for (int i = 0; i < 4; i++) dst[own + i] = vs[i];
    dst[8] = vs[8];
}

__global__ void __launch_bounds__(128, 1) rnn1_kernel(
    const float* __restrict__ x,
    const float* __restrict__ wih_f, const float* __restrict__ whh_f,
    const float* __restrict__ bih_f, const float* __restrict__ bhh_f,
    const float* __restrict__ wih_b, const float* __restrict__ whh_b,
    const float* __restrict__ bih_b, const float* __restrict__ bhh_b,
    int T)
{
    int gtid = blockIdx.x * blockDim.x + threadIdx.x;
    int p = gtid >> 1;     // chain index within direction half
    int r = gtid & 1;      // lane role within pair
    int half = gridDim.x >> 1;
    if (blockIdx.x >= half) {
        rnn1_body<true>(p - (half * (int)blockDim.x >> 1), r,
                        x, wih_b, whh_b, bih_b, bhh_b, T);
    } else {
        rnn1_body<false>(p, r, x, wih_f, whh_f, bih_f, bhh_f, T);
    }
}

// ---------------------------------------------------------------------------
// RNN2 + projection: warp per batch. h broadcast via padded smem rows (no
// shuffles); all 25 h-vectors kept in smem; projection epilogue assigns the
// 75 outputs across lanes.
// ---------------------------------------------------------------------------
#define ROWF 36  // padded row stride in floats (16B-aligned, bank-spread)

__global__ void __launch_bounds__(128) rnn2_kernel(
    const float* __restrict__ wih2, const float* __restrict__ whh2,
    const float* __restrict__ bih2, const float* __restrict__ bhh2,
    const float* __restrict__ wout, const float* __restrict__ bout,
    float* __restrict__ out, int B)
{
    __shared__ __align__(16) float hbuf[4][25 * ROWF];
    __shared__ float wsm[96];

    int tid = threadIdx.x;
    int wid = tid >> 5;
    int lane = tid & 31;
    int b = blockIdx.x * 4 + wid;

    if (tid < 96) wsm[tid] = __ldg(wout + tid);
    __syncthreads();
    if (b >= B) return;

    float WHR[32];
#pragma unroll
    for (int j = 0; j < 32; j++) WHR[j] = SC * __ldg(whh2 + lane * 32 + j);
    float bi = SC * (__ldg(bih2 + lane) + __ldg(bhh2 + lane));

    // step 0: input y from g_y
    const float* yb = g_y + (size_t)b * 18;
    float acc = bi;
#pragma unroll
    for (int j = 0; j < 18; j++)
        acc = fmaf(SC * __ldg(wih2 + lane * 18 + j), __ldg(yb + j), acc);
    float h = tanh_sc(acc);

    float* hr = hbuf[wid];
    hr[lane] = h;
    __syncwarp();

#pragma unroll 1
    for (int t = 1; t < 25; t++) {
        const float4* rp = reinterpret_cast<const float4*>(hr + (t - 1) * ROWF);
        float a = bi;
#pragma unroll
        for (int q = 0; q < 8; q++) {
            float4 v = rp[q];
            a = fmaf(WHR[4 * q + 0], v.x, a);
            a = fmaf(WHR[4 * q + 1], v.y, a);
            a = fmaf(WHR[4 * q + 2], v.z, a);
            a = fmaf(WHR[4 * q + 3], v.w, a);
        }
        h = tanh_sc(a);
        hr[t * ROWF + lane] = h;
        __syncwarp();
    }

    // epilogue: 75 outputs -> lanes (idx = lane, lane+32, lane+64)
    float bo0 = __ldg(bout + 0), bo1 = __ldg(bout + 1), bo2 = __ldg(bout + 2);
    float* ob = out + (size_t)b * 75;
#pragma unroll
    for (int k = 0; k < 3; k++) {
        int idx = lane + 32 * k;
        if (idx < 75) {
            int t = idx / 3;
            int o = idx - 3 * t;
            const float4* rp = reinterpret_cast<const float4*>(hr + t * ROWF);
            float a = (o == 0) ? bo0 : ((o == 1) ? bo1 : bo2);
#pragma unroll
            for (int q = 0; q < 8; q++) {
                float4 v = rp[q];
                a = fmaf(wsm[o * 32 + 4 * q + 0], v.x, a);
                a = fmaf(wsm[o * 32 + 4 * q + 1], v.y, a);
                a = fmaf(wsm[o * 32 + 4 * q + 2], v.z, a);
                a = fmaf(wsm[o * 32 + 4 * q + 3], v.w, a);
            }
            ob[idx] = a;
        }
    }
}

// ---------------------------------------------------------------------------
extern "C" void kernel_launch(void* const* d_in, const int* in_sizes, int n_in,
                              void* d_out, int out_size)
{
    const float* x      = (const float*)d_in[0];
    const float* wih_f  = (const float*)d_in[1];
    const float* whh_f  = (const float*)d_in[2];
    const float* bih_f  = (const float*)d_in[3];
    const float* bhh_f  = (const float*)d_in[4];
    const float* wih_b  = (const float*)d_in[5];
    const float* whh_b  = (const float*)d_in[6];
    const float* bih_b  = (const float*)d_in[7];
    const float* bhh_b  = (const float*)d_in[8];
    const float* wih2   = (const float*)d_in[9];
    const float* whh2   = (const float*)d_in[10];
    const float* bih2   = (const float*)d_in[11];
    const float* bhh2   = (const float*)d_in[12];
    const float* wout   = (const float*)d_in[13];
    const float* bout   = (const float*)d_in[14];
    float* out = (float*)d_out;

    int B = out_size / 75;                 // 4096
    int T = in_sizes[0] / (B * 5);         // 2048

    // 2 lanes per chain, 2*B chains total -> 4*B threads = 128 blocks of 128
    int blocks1 = (4 * B) / 128;           // 128 (first half fwd, second bwd)
    rnn1_kernel<<<blocks1, 128>>>(x, wih_f, whh_f, bih_f, bhh_f,
                                  wih_b, whh_b, bih_b, bhh_b, T);

    rnn2_kernel<<<B / 4, 128>>>(wih2, whh2, bih2, bhh2, wout, bout, out, B);
}